// round 14
// baseline (speedup 1.0000x reference)
#include <cuda_runtime.h>
#include <cstdint>

// ---------------- problem constants ----------------
#define N_NODES 8192
#define KFULL   8192
#define IN_DIM  64
#define OUT_DIM 64
#define SUPPORT 4
#define NB      2                              // num bases

// ---------------- GEMM tiling ----------------
#define BM 128
#define BK 32
#define KSPLIT 2
#define KHALF (KFULL / KSPLIT)                 // 4096
#define K_ITERS (KHALF / BK)                   // 128
#define THREADS 512
#define APITCH 36                              // padded pitch (floats): 144B
#define PITCHB (APITCH * 4)
#define C_TILE_BYTES (BM * PITCHB)             // 18432 per basis
#define CBUF_BYTES (NB * C_TILE_BYTES)         // 36864
#define B_TILE_BYTES (OUT_DIM * PITCHB)        // 9216 per basis
#define BBUF_BYTES (NB * B_TILE_BYTES)         // 18432
#define SMEM_B_OFF (2 * CBUF_BYTES)
#define GEMM_SMEM (2 * CBUF_BYTES + 2 * BBUF_BYTES)   // 110,592 B

// ---------------- device scratch (no allocs allowed) ----------------
__device__ __align__(1024) float g_ZT[NB * OUT_DIM * KFULL];            // 4 MB: ZT[b][n][k]
__device__ __align__(1024) float g_part[KSPLIT * N_NODES * OUT_DIM];    // 4 MB
__device__ int g_cnt[N_NODES / BM];                                     // zero-init, self-resetting

// ---------------- helpers ----------------
__device__ __forceinline__ uint32_t smem_u32(const void* p) {
    uint32_t a;
    asm("{ .reg .u64 t; cvta.to.shared.u64 t, %1; cvt.u32.u64 %0, t; }" : "=r"(a) : "l"(p));
    return a;
}
#define CP_ASYNC16(dst_u32, src_ptr) \
    asm volatile("cp.async.cg.shared.global [%0], [%1], 16;" :: "r"(dst_u32), "l"(src_ptr) : "memory")
#define CP_COMMIT() asm volatile("cp.async.commit_group;" ::: "memory")
#define CP_WAIT(n)  asm volatile("cp.async.wait_group %0;" :: "n"(n) : "memory")

#define LDSM_X4(r0, r1, r2, r3, addr) \
    asm volatile("ldmatrix.sync.aligned.m8n8.x4.shared.b16 {%0,%1,%2,%3}, [%4];" \
        : "=r"(r0), "=r"(r1), "=r"(r2), "=r"(r3) : "r"(addr))

#define STS128(addr, x, y, z, w) \
    asm volatile("st.shared.v4.b32 [%0], {%1,%2,%3,%4};" \
        :: "r"(addr), "r"(x), "r"(y), "r"(z), "r"(w) : "memory")

#define MMA_TF32(c, a, b0, b1) \
    asm volatile("mma.sync.aligned.m16n8k8.row.col.f32.tf32.tf32.f32 " \
        "{%0,%1,%2,%3}, {%4,%5,%6,%7}, {%8,%9}, {%0,%1,%2,%3};" \
        : "+f"((c)[0]), "+f"((c)[1]), "+f"((c)[2]), "+f"((c)[3]) \
        : "r"((a)[0]), "r"((a)[1]), "r"((a)[2]), "r"((a)[3]), "r"(b0), "r"(b1))

__device__ __forceinline__ uint32_t f2tf32(float f) {
    uint32_t u;
    asm("cvt.rna.tf32.f32 %0, %1;" : "=r"(u) : "f"(f));
    return u;
}

// ---------------- kernel 1: ZT[b][n][k] = sum_i X[k,i] * K_b[i,n] ----------------
__global__ void y_kernel(const float* __restrict__ X,
                         const float* __restrict__ Kmat,
                         float* __restrict__ ZT)
{
    __shared__ float Vs[IN_DIM][OUT_DIM + 1];
    __shared__ float Xs[32][IN_DIM + 1];
    const int b  = blockIdx.y;
    const int j0 = blockIdx.x * 32;

    for (int idx = threadIdx.x; idx < IN_DIM * OUT_DIM; idx += blockDim.x) {
        int i = idx >> 6, o = idx & 63;
        Vs[i][o] = Kmat[(b * IN_DIM + i) * OUT_DIM + o];
    }
    for (int idx = threadIdx.x; idx < 32 * IN_DIM; idx += blockDim.x) {
        int j = idx >> 6, i = idx & 63;
        Xs[j][i] = X[(size_t)(j0 + j) * IN_DIM + i];
    }
    __syncthreads();

    const int jq = (threadIdx.x & 7) * 4;
    const int oq = (threadIdx.x >> 3) * 4;
    float acc[4][4] = {};
    #pragma unroll 8
    for (int i = 0; i < IN_DIM; i++) {
        float xv[4], vv[4];
        #pragma unroll
        for (int a = 0; a < 4; a++) xv[a] = Xs[jq + a][i];
        #pragma unroll
        for (int q = 0; q < 4; q++) vv[q] = Vs[i][oq + q];
        #pragma unroll
        for (int a = 0; a < 4; a++)
            #pragma unroll
            for (int q = 0; q < 4; q++)
                acc[a][q] = fmaf(xv[a], vv[q], acc[a][q]);
    }

    uint32_t* zt_u = reinterpret_cast<uint32_t*>(ZT);
    #pragma unroll
    for (int q = 0; q < 4; q++)
        #pragma unroll
        for (int a = 0; a < 4; a++)
            zt_u[((size_t)(b * OUT_DIM) + oq + q) * KFULL + j0 + jq + a] =
                f2tf32(acc[a][q]);
}

// ---------------- kernel 2: combined-basis tf32 GEMM, 512 threads, warp tile 32x16 ----------------
__global__ void __launch_bounds__(THREADS, 1)
rgcn_gemm_kernel(const float* __restrict__ A,
                 const float* __restrict__ ZT,
                 const float* __restrict__ comp,
                 const float* __restrict__ bias,
                 float* __restrict__ part,
                 float* __restrict__ out)
{
    extern __shared__ float sm[];
    const uint32_t sm_base = smem_u32(sm);

    const int tid  = threadIdx.x;
    const int wid  = tid >> 5;
    const int lane = tid & 31;
    const int m0   = blockIdx.x * BM;
    const int kh   = blockIdx.y;
    const size_t kbase0 = (size_t)kh * KHALF;

    // warp grid: 4 (M) x 4 (N); each warp 32 x 16 per basis
    const int mbase = (wid & 3) * 32;
    const int nbase = (wid >> 2) * 16;
    const int lrow  = lane & 7;
    const int ltile = lane >> 3;

    uint32_t aoff[2];
    #pragma unroll
    for (int i = 0; i < 2; i++)
        aoff[i] = (uint32_t)((mbase + 16 * i + lrow + 8 * (ltile & 1)) * PITCHB
                             + 16 * (ltile >> 1));
    // B n16 tile: x4 tiles [n0-7,k0-3],[n0-7,k4-7],[n8-15,k0-3],[n8-15,k4-7]
    const uint32_t boff = (uint32_t)((nbase + lrow + 8 * (ltile >> 1)) * PITCHB
                                     + 16 * (ltile & 1));

    float cb[NB][SUPPORT];
    #pragma unroll
    for (int s = 0; s < SUPPORT; s++)
        #pragma unroll
        for (int b = 0; b < NB; b++)
            cb[b][s] = __ldg(comp + s * NB + b);

    // accumulators: [basis][mtile 0..1][n8 0..1][4]
    float c[NB][2][2][4];
    #pragma unroll
    for (int b = 0; b < NB; b++)
        #pragma unroll
        for (int i = 0; i < 2; i++)
            #pragma unroll
            for (int j = 0; j < 2; j++)
                #pragma unroll
                for (int r = 0; r < 4; r++) c[b][i][j][r] = 0.0f;

    // A loads: 512 threads cover 128 rows x 8 float4; thread owns row tid>>2,
    // float4 cols (tid&3) and (tid&3)+4
    const int arow  = tid >> 2;
    const int acol4 = tid & 3;
    const float4* ap[SUPPORT];
    #pragma unroll
    for (int s = 0; s < SUPPORT; s++)
        ap[s] = reinterpret_cast<const float4*>(
            A + ((size_t)s * KFULL + m0 + arow) * KFULL + kbase0) + acol4;

    const uint32_t c_sts0 = (uint32_t)(arow * PITCHB + acol4 * 16);
    // B loads: vrow = tid>>2 encodes (basis, n-row) as vrow = b*64 + n
    const float* zsrc0 = ZT + (size_t)arow * KFULL + kbase0 + acol4 * 4;
    const int bb   = arow >> 6;
    const int brow = arow & 63;
    const uint32_t b_sts0 = (uint32_t)(bb * B_TILE_BYTES + brow * PITCHB + acol4 * 16);

    float4 areg[SUPPORT][2];
    auto ldgA = [&](int it) {
        const size_t kofs = (size_t)(it * (BK / 4));
        #pragma unroll
        for (int s = 0; s < SUPPORT; s++)
            #pragma unroll
            for (int p = 0; p < 2; p++)
                areg[s][p] = __ldg(ap[s] + kofs + p * 4);
    };

    auto issueB = [&](int it) {
        const uint32_t bs = sm_base + SMEM_B_OFF + (uint32_t)((it & 1) * BBUF_BYTES);
        const size_t kofs = (size_t)it * BK;
        #pragma unroll
        for (int p = 0; p < 2; p++)
            CP_ASYNC16(bs + b_sts0 + (uint32_t)(p * 64), zsrc0 + kofs + p * 16);
    };

    // prologue
    ldgA(0);
    issueB(0); CP_COMMIT();

    for (int it = 0; it < K_ITERS; ++it) {
        // ---- combine A relations -> C_b (tf32) -> smem staging ----
        const uint32_t cs = sm_base + (uint32_t)((it & 1) * CBUF_BYTES);
        #pragma unroll
        for (int p = 0; p < 2; p++) {
            const float4 a0 = areg[0][p], a1 = areg[1][p], a2 = areg[2][p], a3 = areg[3][p];
            #pragma unroll
            for (int b = 0; b < NB; b++) {
                float ox = fmaf(cb[b][3], a3.x, fmaf(cb[b][2], a2.x, fmaf(cb[b][1], a1.x, cb[b][0] * a0.x)));
                float oy = fmaf(cb[b][3], a3.y, fmaf(cb[b][2], a2.y, fmaf(cb[b][1], a1.y, cb[b][0] * a0.y)));
                float oz = fmaf(cb[b][3], a3.z, fmaf(cb[b][2], a2.z, fmaf(cb[b][1], a1.z, cb[b][0] * a0.z)));
                float ow = fmaf(cb[b][3], a3.w, fmaf(cb[b][2], a2.w, fmaf(cb[b][1], a1.w, cb[b][0] * a0.w)));
                STS128(cs + (uint32_t)(b * C_TILE_BYTES + p * 64) + c_sts0,
                       f2tf32(ox), f2tf32(oy), f2tf32(oz), f2tf32(ow));
            }
        }

        // ---- next loads in flight ----
        if (it + 1 < K_ITERS) {
            ldgA(it + 1);
            issueB(it + 1); CP_COMMIT();
            CP_WAIT(1);
        } else {
            CP_WAIT(0);
        }
        __syncthreads();

        // ---- MMA over both bases, 4 kk-steps ----
        const uint32_t csb = sm_base + (uint32_t)((it & 1) * CBUF_BYTES);
        const uint32_t bsb = sm_base + SMEM_B_OFF + (uint32_t)((it & 1) * BBUF_BYTES);
        #pragma unroll
        for (int b = 0; b < NB; b++) {
            const uint32_t ca = csb + (uint32_t)(b * C_TILE_BYTES);
            const uint32_t ba = bsb + (uint32_t)(b * B_TILE_BYTES);
            #pragma unroll
            for (int kk = 0; kk < 4; kk++) {
                const uint32_t ko = (uint32_t)(kk * 32);
                uint32_t af[2][4], bf[4];
                #pragma unroll
                for (int i = 0; i < 2; i++)
                    LDSM_X4(af[i][0], af[i][1], af[i][2], af[i][3], ca + aoff[i] + ko);
                LDSM_X4(bf[0], bf[1], bf[2], bf[3], ba + boff + ko);
                #pragma unroll
                for (int i = 0; i < 2; i++) {
                    #pragma unroll
                    for (int jn = 0; jn < 2; jn++)
                        MMA_TF32(c[b][i][jn], af[i], bf[2 * jn], bf[2 * jn + 1]);
                }
            }
        }
    }

    // ---- write partial (sum of bases) ----
    float* pbase = part + (size_t)kh * N_NODES * OUT_DIM + (size_t)m0 * OUT_DIM;
    const int g = lane >> 2, q2 = (lane & 3) * 2;
    #pragma unroll
    for (int i = 0; i < 2; i++) {
        #pragma unroll
        for (int jn = 0; jn < 2; jn++) {
            const int row = mbase + 16 * i + g;
            const int col = nbase + 8 * jn + q2;
            float2 v0 = make_float2(c[0][i][jn][0] + c[1][i][jn][0],
                                    c[0][i][jn][1] + c[1][i][jn][1]);
            float2 v1 = make_float2(c[0][i][jn][2] + c[1][i][jn][2],
                                    c[0][i][jn][3] + c[1][i][jn][3]);
            *reinterpret_cast<float2*>(pbase + (size_t)row * OUT_DIM + col)       = v0;
            *reinterpret_cast<float2*>(pbase + (size_t)(row + 8) * OUT_DIM + col) = v1;
        }
    }

    // ---- fused finalize: last CTA of this m-tile sums slices + bias + relu ----
    __shared__ int s_last;
    __threadfence();
    __syncthreads();
    if (tid == 0) {
        int old = atomicAdd(&g_cnt[blockIdx.x], 1);
        s_last = (old == KSPLIT - 1);
    }
    __syncthreads();
    if (s_last) {
        __threadfence();
        const float4* p0 = reinterpret_cast<const float4*>(part + (size_t)m0 * OUT_DIM);
        const float4* p1 = reinterpret_cast<const float4*>(part + (size_t)N_NODES * OUT_DIM + (size_t)m0 * OUT_DIM);
        float4* ob = reinterpret_cast<float4*>(out + (size_t)m0 * OUT_DIM);
        #pragma unroll
        for (int i = 0; i < 4; i++) {          // 2048 float4 / 512 threads
            const int v = tid + i * THREADS;
            const int ccol = (v * 4) & (OUT_DIM - 1);
            float4 a = p0[v], b = p1[v], r;
            r.x = fmaxf(a.x + b.x + __ldg(bias + ccol + 0), 0.0f);
            r.y = fmaxf(a.y + b.y + __ldg(bias + ccol + 1), 0.0f);
            r.z = fmaxf(a.z + b.z + __ldg(bias + ccol + 2), 0.0f);
            r.w = fmaxf(a.w + b.w + __ldg(bias + ccol + 3), 0.0f);
            ob[v] = r;
        }
        if (tid == 0) atomicExch(&g_cnt[blockIdx.x], 0);
    }
}

// ---------------- host launcher ----------------
extern "C" void kernel_launch(void* const* d_in, const int* in_sizes, int n_in,
                              void* d_out, int out_size)
{
    const float* features = (const float*)d_in[0];
    const float* A        = (const float*)d_in[1];
    const float* kern     = (const float*)d_in[2];
    const float* comp     = (const float*)d_in[3];
    const float* bias     = (const float*)d_in[4];
    float* out = (float*)d_out;

    float* zt = nullptr;
    float* pt = nullptr;
    cudaGetSymbolAddress((void**)&zt, g_ZT);
    cudaGetSymbolAddress((void**)&pt, g_part);

    // 1) ZT[b] = (X @ K_b)^T, tf32-pre-rounded
    y_kernel<<<dim3(KFULL / 32, NB), 128>>>(features, kern, zt);

    // 2) combined-basis GEMM + fused reduce/bias/relu (512 threads, 16 warps/SM)
    cudaFuncSetAttribute(rgcn_gemm_kernel,
                         cudaFuncAttributeMaxDynamicSharedMemorySize, GEMM_SMEM);
    rgcn_gemm_kernel<<<dim3(N_NODES / BM, KSPLIT), THREADS, GEMM_SMEM>>>(
        A, zt, comp, bias, pt, out);
}

// round 15
// speedup vs baseline: 1.2777x; 1.2777x over previous
#include <cuda_runtime.h>
#include <cstdint>

// ---------------- problem constants ----------------
#define N_NODES 8192
#define KFULL   8192
#define IN_DIM  64
#define OUT_DIM 64
#define SUPPORT 4
#define NB      2                              // num bases

// ---------------- GEMM tiling (R7/R11 equilibrium config) ----------------
#define BM 128
#define BK 32
#define KSPLIT 2
#define KHALF (KFULL / KSPLIT)                 // 4096
#define K_ITERS (KHALF / BK)                   // 128
#define APITCH 36                              // padded pitch (floats): 144B
#define PITCHB (APITCH * 4)
#define C_TILE_BYTES (BM * PITCHB)             // 18432 per basis
#define CBUF_BYTES (NB * C_TILE_BYTES)         // 36864
#define B_TILE_BYTES (OUT_DIM * PITCHB)        // 9216 per basis
#define BBUF_BYTES (NB * B_TILE_BYTES)         // 18432
#define NBSTAGE 3                              // triple-buffered B
#define SMEM_B_OFF (2 * CBUF_BYTES)            // 73728
#define GEMM_SMEM (2 * CBUF_BYTES + NBSTAGE * BBUF_BYTES)   // 129,024 B

// ---------------- device scratch (no allocs allowed) ----------------
__device__ __align__(1024) float g_ZT[NB * OUT_DIM * KFULL];            // 4 MB: ZT[b][n][k]
__device__ __align__(1024) float g_part[KSPLIT * N_NODES * OUT_DIM];    // 4 MB
__device__ int g_cnt[N_NODES / BM];                                     // zero-init, self-resetting

// ---------------- helpers ----------------
__device__ __forceinline__ uint32_t smem_u32(const void* p) {
    uint32_t a;
    asm("{ .reg .u64 t; cvta.to.shared.u64 t, %1; cvt.u32.u64 %0, t; }" : "=r"(a) : "l"(p));
    return a;
}
#define CP_ASYNC16(dst_u32, src_ptr) \
    asm volatile("cp.async.cg.shared.global [%0], [%1], 16;" :: "r"(dst_u32), "l"(src_ptr) : "memory")
#define CP_COMMIT() asm volatile("cp.async.commit_group;" ::: "memory")
#define CP_WAIT(n)  asm volatile("cp.async.wait_group %0;" :: "n"(n) : "memory")

#define LDSM_X4(r0, r1, r2, r3, addr) \
    asm volatile("ldmatrix.sync.aligned.m8n8.x4.shared.b16 {%0,%1,%2,%3}, [%4];" \
        : "=r"(r0), "=r"(r1), "=r"(r2), "=r"(r3) : "r"(addr))

#define STS128(addr, x, y, z, w) \
    asm volatile("st.shared.v4.b32 [%0], {%1,%2,%3,%4};" \
        :: "r"(addr), "r"(x), "r"(y), "r"(z), "r"(w) : "memory")

#define MMA_TF32(c, a, b0, b1) \
    asm volatile("mma.sync.aligned.m16n8k8.row.col.f32.tf32.tf32.f32 " \
        "{%0,%1,%2,%3}, {%4,%5,%6,%7}, {%8,%9}, {%0,%1,%2,%3};" \
        : "+f"((c)[0]), "+f"((c)[1]), "+f"((c)[2]), "+f"((c)[3]) \
        : "r"((a)[0]), "r"((a)[1]), "r"((a)[2]), "r"((a)[3]), "r"(b0), "r"(b1))

__device__ __forceinline__ uint32_t f2tf32(float f) {
    uint32_t u;
    asm("cvt.rna.tf32.f32 %0, %1;" : "=r"(u) : "f"(f));
    return u;
}

// ---------------- kernel 1: ZT[b][n][k] = sum_i X[k,i] * K_b[i,n] ----------------
__global__ void y_kernel(const float* __restrict__ X,
                         const float* __restrict__ Kmat,
                         float* __restrict__ ZT)
{
    __shared__ float Vs[IN_DIM][OUT_DIM + 1];
    __shared__ float Xs[32][IN_DIM + 1];
    const int b  = blockIdx.y;
    const int j0 = blockIdx.x * 32;

    for (int idx = threadIdx.x; idx < IN_DIM * OUT_DIM; idx += blockDim.x) {
        int i = idx >> 6, o = idx & 63;
        Vs[i][o] = Kmat[(b * IN_DIM + i) * OUT_DIM + o];
    }
    for (int idx = threadIdx.x; idx < 32 * IN_DIM; idx += blockDim.x) {
        int j = idx >> 6, i = idx & 63;
        Xs[j][i] = X[(size_t)(j0 + j) * IN_DIM + i];
    }
    __syncthreads();

    const int jq = (threadIdx.x & 7) * 4;
    const int oq = (threadIdx.x >> 3) * 4;
    float acc[4][4] = {};
    #pragma unroll 8
    for (int i = 0; i < IN_DIM; i++) {
        float xv[4], vv[4];
        #pragma unroll
        for (int a = 0; a < 4; a++) xv[a] = Xs[jq + a][i];
        #pragma unroll
        for (int q = 0; q < 4; q++) vv[q] = Vs[i][oq + q];
        #pragma unroll
        for (int a = 0; a < 4; a++)
            #pragma unroll
            for (int q = 0; q < 4; q++)
                acc[a][q] = fmaf(xv[a], vv[q], acc[a][q]);
    }

    uint32_t* zt_u = reinterpret_cast<uint32_t*>(ZT);
    #pragma unroll
    for (int q = 0; q < 4; q++)
        #pragma unroll
        for (int a = 0; a < 4; a++)
            zt_u[((size_t)(b * OUT_DIM) + oq + q) * KFULL + j0 + jq + a] =
                f2tf32(acc[a][q]);
}

// ---------------- kernel 2: combined-basis tf32 GEMM + fused finalize ----------------
__global__ void __launch_bounds__(256, 1)
rgcn_gemm_kernel(const float* __restrict__ A,
                 const float* __restrict__ ZT,
                 const float* __restrict__ comp,
                 const float* __restrict__ bias,
                 float* __restrict__ part,
                 float* __restrict__ out)
{
    extern __shared__ float sm[];
    const uint32_t sm_base = smem_u32(sm);

    const int tid  = threadIdx.x;
    const int wid  = tid >> 5;
    const int lane = tid & 31;
    const int m0   = blockIdx.x * BM;
    const int kh   = blockIdx.y;
    const size_t kbase0 = (size_t)kh * KHALF;

    // warp grid: 4 (M) x 2 (N); each warp 32x32 per basis
    const int mbase = (wid & 3) * 32;
    const int nbase = (wid >> 2) * 32;
    const int lrow  = lane & 7;
    const int ltile = lane >> 3;

    uint32_t aoff[2];
    #pragma unroll
    for (int i = 0; i < 2; i++)
        aoff[i] = (uint32_t)((mbase + 16 * i + lrow + 8 * (ltile & 1)) * PITCHB
                             + 16 * (ltile >> 1));
    uint32_t boff[2];
    #pragma unroll
    for (int p = 0; p < 2; p++)
        boff[p] = (uint32_t)((nbase + 16 * p + lrow + 8 * (ltile >> 1)) * PITCHB
                             + 16 * (ltile & 1));

    float cb[NB][SUPPORT];
    #pragma unroll
    for (int s = 0; s < SUPPORT; s++)
        #pragma unroll
        for (int b = 0; b < NB; b++)
            cb[b][s] = __ldg(comp + s * NB + b);

    // accumulators: [basis][mtile][n8][4]
    float c[NB][2][4][4];
    #pragma unroll
    for (int b = 0; b < NB; b++)
        #pragma unroll
        for (int i = 0; i < 2; i++)
            #pragma unroll
            for (int j = 0; j < 4; j++)
                #pragma unroll
                for (int r = 0; r < 4; r++) c[b][i][j][r] = 0.0f;

    const int arow = tid >> 3;
    const int acol = (tid & 7) * 4;
    const float4* ap[SUPPORT];
    #pragma unroll
    for (int s = 0; s < SUPPORT; s++)
        ap[s] = reinterpret_cast<const float4*>(
            A + ((size_t)s * KFULL + m0 + arow) * KFULL + kbase0 + acol);
    const size_t APSTEP = (size_t)32 * (KFULL / 4);

    const uint32_t c_sts0 = (uint32_t)(arow * PITCHB + acol * 4);
    const float* zsrc0 = ZT + (size_t)arow * KFULL + kbase0 + acol;
    const uint32_t b_sts0 = c_sts0;

    float4 areg[SUPPORT][4];
    auto ldgA = [&](int it) {
        const size_t kofs = (size_t)(it * (BK / 4));
        #pragma unroll
        for (int s = 0; s < SUPPORT; s++)
            #pragma unroll
            for (int p = 0; p < 4; p++)
                areg[s][p] = __ldg(ap[s] + kofs + (size_t)p * APSTEP);
    };

    auto issueB = [&](int it) {
        const uint32_t bs = sm_base + SMEM_B_OFF + (uint32_t)((it % NBSTAGE) * BBUF_BYTES);
        const size_t kofs = (size_t)it * BK;
        #pragma unroll
        for (int b = 0; b < NB; b++)
            #pragma unroll
            for (int h = 0; h < 2; h++) {
                const float* src = zsrc0 + ((size_t)(b * OUT_DIM + h * 32) * KFULL) + kofs;
                const uint32_t dst = bs + (uint32_t)(b * B_TILE_BYTES + h * 32 * PITCHB) + b_sts0;
                CP_ASYNC16(dst, src);
            }
        CP_COMMIT();
    };

    // prologue: B(0), B(1) in flight; areg = A(0)
    ldgA(0);
    issueB(0);
    issueB(1);

    for (int it = 0; it < K_ITERS; ++it) {
        // ---- combine A -> C_b with ldgA(it+1) interleaved per p-slice ----
        const uint32_t cs = sm_base + (uint32_t)((it & 1) * CBUF_BYTES);
        const bool more = (it + 1 < K_ITERS);
        const size_t nkofs = (size_t)((it + 1) * (BK / 4));
        #pragma unroll
        for (int p = 0; p < 4; p++) {
            // snapshot this slice, then immediately re-issue its loads for it+1
            const float4 a0 = areg[0][p], a1 = areg[1][p], a2 = areg[2][p], a3 = areg[3][p];
            if (more) {
                #pragma unroll
                for (int s = 0; s < SUPPORT; s++)
                    areg[s][p] = __ldg(ap[s] + nkofs + (size_t)p * APSTEP);
            }
            #pragma unroll
            for (int b = 0; b < NB; b++) {
                float ox = fmaf(cb[b][3], a3.x, fmaf(cb[b][2], a2.x, fmaf(cb[b][1], a1.x, cb[b][0] * a0.x)));
                float oy = fmaf(cb[b][3], a3.y, fmaf(cb[b][2], a2.y, fmaf(cb[b][1], a1.y, cb[b][0] * a0.y)));
                float oz = fmaf(cb[b][3], a3.z, fmaf(cb[b][2], a2.z, fmaf(cb[b][1], a1.z, cb[b][0] * a0.z)));
                float ow = fmaf(cb[b][3], a3.w, fmaf(cb[b][2], a2.w, fmaf(cb[b][1], a1.w, cb[b][0] * a0.w)));
                STS128(cs + (uint32_t)(b * C_TILE_BYTES + p * 32 * PITCHB) + c_sts0,
                       f2tf32(ox), f2tf32(oy), f2tf32(oz), f2tf32(ow));
            }
        }

        // ---- keep B two ahead; ensure B(it) landed ----
        if (it + 2 < K_ITERS) {
            issueB(it + 2);
            CP_WAIT(2);
        } else {
            CP_WAIT(0);
        }
        __syncthreads();

        // ---- MMA over both bases ----
        const uint32_t csb = sm_base + (uint32_t)((it & 1) * CBUF_BYTES);
        const uint32_t bsb = sm_base + SMEM_B_OFF + (uint32_t)((it % NBSTAGE) * BBUF_BYTES);
        #pragma unroll
        for (int b = 0; b < NB; b++) {
            const uint32_t ca = csb + (uint32_t)(b * C_TILE_BYTES);
            const uint32_t ba = bsb + (uint32_t)(b * B_TILE_BYTES);
            #pragma unroll
            for (int kk = 0; kk < 4; kk++) {
                const uint32_t ko = (uint32_t)(kk * 32);
                uint32_t af[2][4], bf[2][4];
                #pragma unroll
                for (int i = 0; i < 2; i++)
                    LDSM_X4(af[i][0], af[i][1], af[i][2], af[i][3], ca + aoff[i] + ko);
                #pragma unroll
                for (int p = 0; p < 2; p++)
                    LDSM_X4(bf[p][0], bf[p][1], bf[p][2], bf[p][3], ba + boff[p] + ko);
                #pragma unroll
                for (int i = 0; i < 2; i++) {
                    #pragma unroll
                    for (int jn = 0; jn < 4; jn++) {
                        const int p = jn >> 1, q = jn & 1;
                        MMA_TF32(c[b][i][jn], af[i], bf[p][2 * q], bf[p][2 * q + 1]);
                    }
                }
            }
        }
    }

    // ---- write partial (sum of bases) ----
    float* pbase = part + (size_t)kh * N_NODES * OUT_DIM + (size_t)m0 * OUT_DIM;
    const int g = lane >> 2, q2 = (lane & 3) * 2;
    #pragma unroll
    for (int i = 0; i < 2; i++) {
        #pragma unroll
        for (int jn = 0; jn < 4; jn++) {
            const int row = mbase + 16 * i + g;
            const int col = nbase + 8 * jn + q2;
            float2 v0 = make_float2(c[0][i][jn][0] + c[1][i][jn][0],
                                    c[0][i][jn][1] + c[1][i][jn][1]);
            float2 v1 = make_float2(c[0][i][jn][2] + c[1][i][jn][2],
                                    c[0][i][jn][3] + c[1][i][jn][3]);
            *reinterpret_cast<float2*>(pbase + (size_t)row * OUT_DIM + col)       = v0;
            *reinterpret_cast<float2*>(pbase + (size_t)(row + 8) * OUT_DIM + col) = v1;
        }
    }

    // ---- fused finalize: last CTA of this m-tile sums slices + bias + relu ----
    __shared__ int s_last;
    __threadfence();
    __syncthreads();
    if (tid == 0) {
        int old = atomicAdd(&g_cnt[blockIdx.x], 1);
        s_last = (old == KSPLIT - 1);
    }
    __syncthreads();
    if (s_last) {
        __threadfence();
        const float4* p0 = reinterpret_cast<const float4*>(part + (size_t)m0 * OUT_DIM);
        const float4* p1 = reinterpret_cast<const float4*>(part + (size_t)N_NODES * OUT_DIM + (size_t)m0 * OUT_DIM);
        float4* ob = reinterpret_cast<float4*>(out + (size_t)m0 * OUT_DIM);
        #pragma unroll
        for (int i = 0; i < 8; i++) {
            const int v = tid + i * 256;
            const int ccol = (v * 4) & (OUT_DIM - 1);
            float4 a = p0[v], b = p1[v], r;
            r.x = fmaxf(a.x + b.x + __ldg(bias + ccol + 0), 0.0f);
            r.y = fmaxf(a.y + b.y + __ldg(bias + ccol + 1), 0.0f);
            r.z = fmaxf(a.z + b.z + __ldg(bias + ccol + 2), 0.0f);
            r.w = fmaxf(a.w + b.w + __ldg(bias + ccol + 3), 0.0f);
            ob[v] = r;
        }
        if (tid == 0) atomicExch(&g_cnt[blockIdx.x], 0);
    }
}

// ---------------- host launcher ----------------
extern "C" void kernel_launch(void* const* d_in, const int* in_sizes, int n_in,
                              void* d_out, int out_size)
{
    const float* features = (const float*)d_in[0];
    const float* A        = (const float*)d_in[1];
    const float* kern     = (const float*)d_in[2];
    const float* comp     = (const float*)d_in[3];
    const float* bias     = (const float*)d_in[4];
    float* out = (float*)d_out;

    float* zt = nullptr;
    float* pt = nullptr;
    cudaGetSymbolAddress((void**)&zt, g_ZT);
    cudaGetSymbolAddress((void**)&pt, g_part);

    // 1) ZT[b] = (X @ K_b)^T, tf32-pre-rounded
    y_kernel<<<dim3(KFULL / 32, NB), 128>>>(features, kern, zt);

    // 2) combined-basis GEMM + fused reduce/bias/relu
    cudaFuncSetAttribute(rgcn_gemm_kernel,
                         cudaFuncAttributeMaxDynamicSharedMemorySize, GEMM_SMEM);
    rgcn_gemm_kernel<<<dim3(N_NODES / BM, KSPLIT), 256, GEMM_SMEM>>>(
        A, zt, comp, bias, pt, out);
}

// round 16
// speedup vs baseline: 1.3005x; 1.0178x over previous
#include <cuda_runtime.h>
#include <cstdint>

// ---------------- problem constants ----------------
#define N_NODES 8192
#define KFULL   8192
#define IN_DIM  64
#define OUT_DIM 64
#define SUPPORT 4
#define NB      2                              // num bases

// ---------------- GEMM tiling ----------------
#define BM 128
#define BK 32
#define KSPLIT 2
#define KHALF (KFULL / KSPLIT)                 // 4096
#define K_ITERS (KHALF / BK)                   // 128
#define APITCH 36                              // padded pitch (floats): 144B
#define PITCHB (APITCH * 4)
#define C_TILE_BYTES (BM * PITCHB)             // 18432 per basis
#define CBUF_BYTES (NB * C_TILE_BYTES)         // 36864
#define B_TILE_BYTES (OUT_DIM * PITCHB)        // 9216 per basis
#define BBUF_BYTES (NB * B_TILE_BYTES)         // 18432
#define SMEM_B_OFF (2 * CBUF_BYTES)
#define GEMM_SMEM (2 * CBUF_BYTES + 2 * BBUF_BYTES)   // 110,592 B

// ---------------- device scratch (no allocs allowed) ----------------
__device__ __align__(1024) float g_ZT[NB * OUT_DIM * KFULL];            // 4 MB: ZT[b][n][k]
__device__ __align__(1024) float g_part[KSPLIT * N_NODES * OUT_DIM];    // 4 MB

// ---------------- helpers ----------------
__device__ __forceinline__ uint32_t smem_u32(const void* p) {
    uint32_t a;
    asm("{ .reg .u64 t; cvta.to.shared.u64 t, %1; cvt.u32.u64 %0, t; }" : "=r"(a) : "l"(p));
    return a;
}
#define CP_ASYNC16(dst_u32, src_ptr) \
    asm volatile("cp.async.cg.shared.global [%0], [%1], 16;" :: "r"(dst_u32), "l"(src_ptr) : "memory")
#define CP_COMMIT() asm volatile("cp.async.commit_group;" ::: "memory")
#define CP_WAIT(n)  asm volatile("cp.async.wait_group %0;" :: "n"(n) : "memory")

#define LDSM_X4(r0, r1, r2, r3, addr) \
    asm volatile("ldmatrix.sync.aligned.m8n8.x4.shared.b16 {%0,%1,%2,%3}, [%4];" \
        : "=r"(r0), "=r"(r1), "=r"(r2), "=r"(r3) : "r"(addr))

#define STS128(addr, x, y, z, w) \
    asm volatile("st.shared.v4.b32 [%0], {%1,%2,%3,%4};" \
        :: "r"(addr), "r"(x), "r"(y), "r"(z), "r"(w) : "memory")

#define MMA_TF32(c, a, b0, b1) \
    asm volatile("mma.sync.aligned.m16n8k8.row.col.f32.tf32.tf32.f32 " \
        "{%0,%1,%2,%3}, {%4,%5,%6,%7}, {%8,%9}, {%0,%1,%2,%3};" \
        : "+f"((c)[0]), "+f"((c)[1]), "+f"((c)[2]), "+f"((c)[3]) \
        : "r"((a)[0]), "r"((a)[1]), "r"((a)[2]), "r"((a)[3]), "r"(b0), "r"(b1))

__device__ __forceinline__ uint32_t f2tf32(float f) {
    uint32_t u;
    asm("cvt.rna.tf32.f32 %0, %1;" : "=r"(u) : "f"(f));
    return u;
}

// ---------------- kernel 1: ZT[b][n][k] = sum_i X[k,i] * K_b[i,n] ----------------
__global__ void y_kernel(const float* __restrict__ X,
                         const float* __restrict__ Kmat,
                         float* __restrict__ ZT)
{
    __shared__ float Vs[IN_DIM][OUT_DIM + 1];
    __shared__ float Xs[64][IN_DIM + 1];
    const int b  = blockIdx.y;                  // basis
    const int j0 = blockIdx.x * 64;

    for (int idx = threadIdx.x; idx < IN_DIM * OUT_DIM; idx += blockDim.x) {
        int i = idx >> 6, o = idx & 63;
        Vs[i][o] = Kmat[(b * IN_DIM + i) * OUT_DIM + o];
    }
    for (int idx = threadIdx.x; idx < 64 * IN_DIM; idx += blockDim.x) {
        int j = idx >> 6, i = idx & 63;
        Xs[j][i] = X[(size_t)(j0 + j) * IN_DIM + i];
    }
    __syncthreads();

    const int jq = (threadIdx.x & 15) * 4;
    const int oq = (threadIdx.x >> 4) * 4;
    float acc[4][4] = {};
    #pragma unroll 8
    for (int i = 0; i < IN_DIM; i++) {
        float xv[4], vv[4];
        #pragma unroll
        for (int a = 0; a < 4; a++) xv[a] = Xs[jq + a][i];
        #pragma unroll
        for (int q = 0; q < 4; q++) vv[q] = Vs[i][oq + q];
        #pragma unroll
        for (int a = 0; a < 4; a++)
            #pragma unroll
            for (int q = 0; q < 4; q++)
                acc[a][q] = fmaf(xv[a], vv[q], acc[a][q]);
    }

    uint32_t* zt_u = reinterpret_cast<uint32_t*>(ZT);
    #pragma unroll
    for (int q = 0; q < 4; q++)
        #pragma unroll
        for (int a = 0; a < 4; a++)
            zt_u[((size_t)(b * OUT_DIM) + oq + q) * KFULL + j0 + jq + a] =
                f2tf32(acc[a][q]);
}

// ---------------- kernel 2: combined-basis tf32 GEMM ----------------
// part[kh][m,n] = sum_b sum_{k in half kh} C_b[m,k] * Z_b[k,n],
//   C_b combined in registers from the 4 relation slices of A.
__global__ void __launch_bounds__(256, 1)
rgcn_gemm_kernel(const float* __restrict__ A,
                 const float* __restrict__ ZT,
                 const float* __restrict__ comp,
                 float* __restrict__ part)
{
    extern __shared__ float sm[];
    const uint32_t sm_base = smem_u32(sm);

    const int tid  = threadIdx.x;
    const int wid  = tid >> 5;
    const int lane = tid & 31;
    const int m0   = blockIdx.x * BM;
    const int kh   = blockIdx.y;
    const size_t kbase0 = (size_t)kh * KHALF;

    // warp grid: 4 (M) x 2 (N); each warp 32x32 per basis
    const int mbase = (wid & 3) * 32;
    const int nbase = (wid >> 2) * 32;
    const int lrow  = lane & 7;
    const int ltile = lane >> 3;

    uint32_t aoff[2];
    #pragma unroll
    for (int i = 0; i < 2; i++)
        aoff[i] = (uint32_t)((mbase + 16 * i + lrow + 8 * (ltile & 1)) * PITCHB
                             + 16 * (ltile >> 1));
    uint32_t boff[2];
    #pragma unroll
    for (int p = 0; p < 2; p++)
        boff[p] = (uint32_t)((nbase + 16 * p + lrow + 8 * (ltile >> 1)) * PITCHB
                             + 16 * (ltile & 1));

    // comp coefficients: cb[b][s]
    float cb[NB][SUPPORT];
    #pragma unroll
    for (int s = 0; s < SUPPORT; s++)
        #pragma unroll
        for (int b = 0; b < NB; b++)
            cb[b][s] = __ldg(comp + s * NB + b);

    // accumulators: [basis][mtile][n8][4]
    float c[NB][2][4][4];
    #pragma unroll
    for (int b = 0; b < NB; b++)
        #pragma unroll
        for (int i = 0; i < 2; i++)
            #pragma unroll
            for (int j = 0; j < 4; j++)
                #pragma unroll
                for (int r = 0; r < 4; r++) c[b][i][j][r] = 0.0f;

    // A LDG addressing: thread owns row r = tid>>3 (+32p), col chunk (tid&7)*4
    const int arow = tid >> 3;
    const int acol = (tid & 7) * 4;
    const float4* ap[SUPPORT];
    #pragma unroll
    for (int s = 0; s < SUPPORT; s++)
        ap[s] = reinterpret_cast<const float4*>(
            A + ((size_t)s * KFULL + m0 + arow) * KFULL + kbase0 + acol);
    const size_t APSTEP = (size_t)32 * (KFULL / 4);   // +32 rows, in float4

    // C staging STS addresses (per p, per basis)
    const uint32_t c_sts0 = (uint32_t)(arow * PITCHB + acol * 4);

    // B (ZT) cp.async: thread handles rows {r, r+32} for each basis, r = tid>>3
    const float* zsrc0 = ZT + (size_t)arow * KFULL + kbase0 + acol;
    const uint32_t b_sts0 = (uint32_t)(arow * PITCHB + acol * 4);

    float4 areg[SUPPORT][4];
    auto ldgA = [&](int it) {
        const size_t kofs = (size_t)(it * (BK / 4));   // float4 step per iter
        #pragma unroll
        for (int s = 0; s < SUPPORT; s++)
            #pragma unroll
            for (int p = 0; p < 4; p++)
                areg[s][p] = __ldg(ap[s] + kofs + (size_t)p * APSTEP);
    };

    auto issueB = [&](int it) {
        const uint32_t bs = sm_base + SMEM_B_OFF + (uint32_t)((it & 1) * BBUF_BYTES);
        const size_t kofs = (size_t)it * BK;
        #pragma unroll
        for (int b = 0; b < NB; b++)
            #pragma unroll
            for (int h = 0; h < 2; h++) {
                const float* src = zsrc0 + ((size_t)(b * OUT_DIM + h * 32) * KFULL) + kofs;
                const uint32_t dst = bs + (uint32_t)(b * B_TILE_BYTES + h * 32 * PITCHB) + b_sts0;
                CP_ASYNC16(dst, src);
            }
    };

    // prologue
    ldgA(0);
    issueB(0); CP_COMMIT();

    for (int it = 0; it < K_ITERS; ++it) {
        // ---- combine A relations -> C_b (tf32) -> smem staging ----
        const uint32_t cs = sm_base + (uint32_t)((it & 1) * CBUF_BYTES);
        #pragma unroll
        for (int p = 0; p < 4; p++) {
            const float4 a0 = areg[0][p], a1 = areg[1][p], a2 = areg[2][p], a3 = areg[3][p];
            #pragma unroll
            for (int b = 0; b < NB; b++) {
                float ox = fmaf(cb[b][3], a3.x, fmaf(cb[b][2], a2.x, fmaf(cb[b][1], a1.x, cb[b][0] * a0.x)));
                float oy = fmaf(cb[b][3], a3.y, fmaf(cb[b][2], a2.y, fmaf(cb[b][1], a1.y, cb[b][0] * a0.y)));
                float oz = fmaf(cb[b][3], a3.z, fmaf(cb[b][2], a2.z, fmaf(cb[b][1], a1.z, cb[b][0] * a0.z)));
                float ow = fmaf(cb[b][3], a3.w, fmaf(cb[b][2], a2.w, fmaf(cb[b][1], a1.w, cb[b][0] * a0.w)));
                STS128(cs + (uint32_t)(b * C_TILE_BYTES + p * 32 * PITCHB) + c_sts0,
                       f2tf32(ox), f2tf32(oy), f2tf32(oz), f2tf32(ow));
            }
        }

        // ---- next loads in flight ----
        if (it + 1 < K_ITERS) {
            ldgA(it + 1);
            issueB(it + 1); CP_COMMIT();
            CP_WAIT(1);
        } else {
            CP_WAIT(0);
        }
        __syncthreads();

        // ---- MMA over both bases ----
        const uint32_t csb = sm_base + (uint32_t)((it & 1) * CBUF_BYTES);
        const uint32_t bsb = sm_base + SMEM_B_OFF + (uint32_t)((it & 1) * BBUF_BYTES);
        #pragma unroll
        for (int b = 0; b < NB; b++) {
            const uint32_t ca = csb + (uint32_t)(b * C_TILE_BYTES);
            const uint32_t ba = bsb + (uint32_t)(b * B_TILE_BYTES);
            #pragma unroll
            for (int kk = 0; kk < 4; kk++) {
                const uint32_t ko = (uint32_t)(kk * 32);
                uint32_t af[2][4], bf[2][4];
                #pragma unroll
                for (int i = 0; i < 2; i++)
                    LDSM_X4(af[i][0], af[i][1], af[i][2], af[i][3], ca + aoff[i] + ko);
                #pragma unroll
                for (int p = 0; p < 2; p++)
                    LDSM_X4(bf[p][0], bf[p][1], bf[p][2], bf[p][3], ba + boff[p] + ko);
                #pragma unroll
                for (int i = 0; i < 2; i++) {
                    #pragma unroll
                    for (int jn = 0; jn < 4; jn++) {
                        const int p = jn >> 1, q = jn & 1;
                        MMA_TF32(c[b][i][jn], af[i], bf[p][2 * q], bf[p][2 * q + 1]);
                    }
                }
            }
        }
    }

    // ---- epilogue: sum bases, write partial ----
    float* pbase = part + (size_t)kh * N_NODES * OUT_DIM + (size_t)m0 * OUT_DIM;
    const int g = lane >> 2, q2 = (lane & 3) * 2;
    #pragma unroll
    for (int i = 0; i < 2; i++) {
        #pragma unroll
        for (int jn = 0; jn < 4; jn++) {
            const int row = mbase + 16 * i + g;
            const int col = nbase + 8 * jn + q2;
            float2 v0 = make_float2(c[0][i][jn][0] + c[1][i][jn][0],
                                    c[0][i][jn][1] + c[1][i][jn][1]);
            float2 v1 = make_float2(c[0][i][jn][2] + c[1][i][jn][2],
                                    c[0][i][jn][3] + c[1][i][jn][3]);
            *reinterpret_cast<float2*>(pbase + (size_t)row * OUT_DIM + col)       = v0;
            *reinterpret_cast<float2*>(pbase + (size_t)(row + 8) * OUT_DIM + col) = v1;
        }
    }
}

// ---------------- kernel 3: reduce + bias + relu ----------------
__global__ void reduce_kernel(const float* __restrict__ part,
                              const float* __restrict__ bias,
                              float* __restrict__ out)
{
    const int v = blockIdx.x * blockDim.x + threadIdx.x;   // float4 index
    const int idx = v * 4;
    const int c = idx & (OUT_DIM - 1);
    float4 p0 = *reinterpret_cast<const float4*>(part + idx);
    float4 p1 = *reinterpret_cast<const float4*>(part + (size_t)N_NODES * OUT_DIM + idx);
    float4 r;
    r.x = fmaxf(p0.x + p1.x + __ldg(bias + c + 0), 0.0f);
    r.y = fmaxf(p0.y + p1.y + __ldg(bias + c + 1), 0.0f);
    r.z = fmaxf(p0.z + p1.z + __ldg(bias + c + 2), 0.0f);
    r.w = fmaxf(p0.w + p1.w + __ldg(bias + c + 3), 0.0f);
    *reinterpret_cast<float4*>(out + idx) = r;
}

// ---------------- host launcher ----------------
extern "C" void kernel_launch(void* const* d_in, const int* in_sizes, int n_in,
                              void* d_out, int out_size)
{
    const float* features = (const float*)d_in[0];
    const float* A        = (const float*)d_in[1];
    const float* kern     = (const float*)d_in[2];
    const float* comp     = (const float*)d_in[3];
    const float* bias     = (const float*)d_in[4];
    float* out = (float*)d_out;

    float* zt = nullptr;
    float* pt = nullptr;
    cudaGetSymbolAddress((void**)&zt, g_ZT);
    cudaGetSymbolAddress((void**)&pt, g_part);

    // 1) ZT[b] = (X @ K_b)^T, tf32-pre-rounded
    y_kernel<<<dim3(KFULL / 64, NB), 256>>>(features, kern, zt);

    // 2) combined-basis GEMM into K-split partials
    cudaFuncSetAttribute(rgcn_gemm_kernel,
                         cudaFuncAttributeMaxDynamicSharedMemorySize, GEMM_SMEM);
    rgcn_gemm_kernel<<<dim3(N_NODES / BM, KSPLIT), 256, GEMM_SMEM>>>(A, zt, comp, pt);

    // 3) reduce partials + bias + relu
    reduce_kernel<<<(N_NODES * OUT_DIM / 4) / 256, 256>>>(pt, bias, out);
}